// round 6
// baseline (speedup 1.0000x reference)
#include <cuda_runtime.h>
#include <cstdint>
#include <cstddef>

// Router: top-1 MoE routing with capacity constraint — SINGLE kernel launch.
// Outputs (float32): dispatch[N,8,Ccap], combine[N,8,Ccap], z, aux, div, std
//
// Block roles (grid = 2368 x 256):
//   [0,32)     token: softmax/argmax -> keys + loss partials, then fill slice
//   [32,288)   rank : spin on token_done, branchless stable rank from L2
//   [288,2368) fill : zero-fill slice (with [0,32) after token) at DRAM roofline
//   last block to finish: sparse scatter (<=16K stores) + scalars + counter reset

#define E 8
#define MAXN 8192
#define NACC 55   // 0:z  1..8:psum  9..16:cnt  17..52:G(upper tri 36)  53:sum  54:sumsq
#define TBLOCKS 32
#define RBLOCKS 256
#define GRID    2368
#define FILLERS (GRID - RBLOCKS)   // 2112

__device__ unsigned long long g_fkey[MAXN];   // [e:3][p_bits:32][invidx:13]
__device__ float g_prob[MAXN];
__device__ int   g_rank[MAXN];
__device__ float g_part[TBLOCKS][NACC];
__device__ int   g_tok_done = 0;
__device__ int   g_done     = 0;

__global__ void __launch_bounds__(256, 4)
router_kernel(uint4* __restrict__ out4, size_t n4,
              const float* __restrict__ logits,
              float* __restrict__ dispatch_out,
              float* __restrict__ combine_out,
              float* __restrict__ scalars_out,
              float* __restrict__ out_f, int out_size,
              int N, int Ccap) {
    const int bid = blockIdx.x;
    const int tid = threadIdx.x;
    const int lane = tid & 31;
    const int wid  = tid >> 5;

    // ================= token blocks =================
    if (bid < TBLOCKS) {
        int i = bid * blockDim.x + tid;
        float vals[NACC];
#pragma unroll
        for (int k = 0; k < NACC; k++) vals[k] = 0.0f;

        if (i < N) {
            float4 r0 = reinterpret_cast<const float4*>(logits)[2 * i + 0];
            float4 r1 = reinterpret_cast<const float4*>(logits)[2 * i + 1];
            float raw[E] = {r0.x, r0.y, r0.z, r0.w, r1.x, r1.y, r1.z, r1.w};

            float l[E];
            float s = 0.f, s2 = 0.f;
#pragma unroll
            for (int j = 0; j < E; j++) {
                s  += raw[j];
                s2 += raw[j] * raw[j];
                float c = fminf(fmaxf(raw[j], -10.0f), 10.0f);
                l[j] = c / 1.5f;                 // IEEE div, matches JAX clip/temp
            }
            vals[53] = s;
            vals[54] = s2;

            float m = l[0]; int e = 0;
#pragma unroll
            for (int j = 1; j < E; j++) {
                if (l[j] > m) { m = l[j]; e = j; }
            }

            float sumexp = 0.f;
            float ex[E];
#pragma unroll
            for (int j = 0; j < E; j++) { ex[j] = expf(l[j] - m); sumexp += ex[j]; }
#pragma unroll
            for (int j = 0; j < E; j++) vals[1 + j] = ex[j] / sumexp;
#pragma unroll
            for (int j = 0; j < E; j++) vals[9 + j] = (e == j) ? 1.0f : 0.0f;

            float p = 1.0f / sumexp;             // probs[argmax] exactly as JAX
            g_prob[i] = p;
            unsigned long long key = (unsigned long long)__float_as_uint(p);
            g_fkey[i] = ((unsigned long long)e << 45) | (key << 13)
                      | (unsigned long long)(unsigned)(MAXN - 1 - i);

            float lse = m + logf(sumexp);
            vals[0] = lse * lse;

            int t = 0;
#pragma unroll
            for (int a = 0; a < E; a++)
#pragma unroll
                for (int b = a; b < E; b++) vals[17 + t++] = l[a] * l[b];
        }

#pragma unroll
        for (int k = 0; k < NACC; k++) {
            float v = vals[k];
            v += __shfl_down_sync(0xffffffffu, v, 16);
            v += __shfl_down_sync(0xffffffffu, v, 8);
            v += __shfl_down_sync(0xffffffffu, v, 4);
            v += __shfl_down_sync(0xffffffffu, v, 2);
            v += __shfl_down_sync(0xffffffffu, v, 1);
            vals[k] = v;
        }
        __shared__ float sAcc[8][NACC];
        if (lane == 0) {
#pragma unroll
            for (int k = 0; k < NACC; k++) sAcc[wid][k] = vals[k];
        }
        __syncthreads();
        for (int k = tid; k < NACC; k += blockDim.x) {
            float v = 0.f;
#pragma unroll
            for (int w = 0; w < 8; w++) v += sAcc[w][k];
            g_part[bid][k] = v;
        }
        // publish token results
        __syncthreads();
        __threadfence();
        if (tid == 0) atomicAdd(&g_tok_done, 1);
        // fall through to fill below
    }

    // ================= rank blocks =================
    if (bid >= TBLOCKS && bid < TBLOCKS + RBLOCKS) {
        if (tid == 0) {
            while (*((volatile int*)&g_tok_done) < TBLOCKS) __nanosleep(64);
        }
        __syncthreads();
        __threadfence();

        int rb = bid - TBLOCKS;                  // 0..255
        int base = (rb * 8 + wid) * 4;           // this warp's 4 tokens

        unsigned long long fki[4], up[4];
        int cnt[4] = {0, 0, 0, 0};
#pragma unroll
        for (int t = 0; t < 4; t++) {
            int tok = base + t;
            unsigned long long f = (tok < N) ? g_fkey[tok] : ~0ull;
            fki[t] = f;
            up[t]  = (((f >> 45) + 1ull) << 45);
        }

        int n32 = MAXN >> 5;                     // 256 iterations per lane
#pragma unroll 8
        for (int it = 0; it < n32; ++it) {
            int j = it * 32 + lane;
            unsigned long long fk = (j < N) ? g_fkey[j] : 0ull;  // 0 never counts
#pragma unroll
            for (int t = 0; t < 4; t++)
                cnt[t] += (int)((fk > fki[t]) & (fk < up[t]));
        }

#pragma unroll
        for (int t = 0; t < 4; t++) {
            int v = cnt[t];
            v += __shfl_down_sync(0xffffffffu, v, 16);
            v += __shfl_down_sync(0xffffffffu, v, 8);
            v += __shfl_down_sync(0xffffffffu, v, 4);
            v += __shfl_down_sync(0xffffffffu, v, 2);
            v += __shfl_down_sync(0xffffffffu, v, 1);
            cnt[t] = v;                          // valid on lane 0
        }
        if (lane == 0) {
#pragma unroll
            for (int t = 0; t < 4; t++) {
                int tok = base + t;
                if (tok < N) g_rank[tok] = cnt[t];
            }
        }
    } else {
        // ================= fill path (token blocks + dedicated fillers) ======
        int fid = (bid < TBLOCKS) ? bid : (bid - RBLOCKS);   // 0..FILLERS-1
        const uint4 z = make_uint4(0u, 0u, 0u, 0u);
        size_t i = (size_t)fid * blockDim.x + tid;
        size_t stride = (size_t)FILLERS * blockDim.x;
        for (; i < n4; i += stride) out4[i] = z;
    }

    // ================= completion + last-block epilogue =================
    __syncthreads();
    __threadfence();
    __shared__ int sIsLast;
    if (tid == 0) {
        int ticket = atomicAdd(&g_done, 1);
        sIsLast = (ticket == GRID - 1);
    }
    __syncthreads();

    if (sIsLast) {
        __threadfence();                          // acquire: see all blocks' work

        // tail floats not covered by uint4 fill (none when out_size%4==0)
        for (int k = (int)(n4 << 2) + tid; k < out_size; k += blockDim.x)
            out_f[k] = 0.0f;

        // sparse scatter: <=2 stores per token
        for (int tok = tid; tok < N; tok += blockDim.x) {
            int rank = g_rank[tok];
            if (rank < Ccap) {
                int e = (int)(g_fkey[tok] >> 45);
                float p = g_prob[tok];
                size_t b = ((size_t)tok * E + e) * (size_t)Ccap + (size_t)rank;
                dispatch_out[b] = 1.0f;
                combine_out[b]  = p;
            }
        }

        // fold partials + scalars
        __shared__ float sAccF[NACC];
        if (tid < NACC) {
            float v = 0.f;
#pragma unroll
            for (int r = 0; r < TBLOCKS; r++) v += g_part[r][tid];
            sAccF[tid] = v;
        }
        __syncthreads();
        if (tid == 0) {
            float z_loss = sAccF[0] / (float)N;

            float aux = 0.f;
            for (int e = 0; e < E; e++) aux += sAccF[9 + e] * sAccF[1 + e];
            aux = aux * (float)E / ((float)N * (float)N);

            float G[E][E];
            int t = 0;
            for (int a = 0; a < E; a++)
                for (int b = a; b < E; b++) { G[a][b] = sAccF[17 + t]; G[b][a] = sAccF[17 + t]; t++; }
            float nrm[E];
            for (int a = 0; a < E; a++) nrm[a] = fmaxf(sqrtf(G[a][a]), 1e-12f);
            float div = 0.f;
            for (int a = 0; a < E; a++)
                for (int b = a + 1; b < E; b++) {
                    float c = G[a][b] / (nrm[a] * nrm[b]);
                    div += 2.0f * c * c;
                }
            div /= (float)(E * (E - 1));

            double M = (double)N * E;
            double sm = (double)sAccF[53], sq = (double)sAccF[54];
            double var = (sq - sm * sm / M) / (M - 1.0);

            scalars_out[0] = z_loss;
            scalars_out[1] = aux;
            scalars_out[2] = div;
            scalars_out[3] = (float)sqrt(var);

            // reset counters for next (identical) replay
            __threadfence();
            g_done = 0;
            g_tok_done = 0;
        }
    }
}

// -------------------------------------------------------------- launch ----
extern "C" void kernel_launch(void* const* d_in, const int* in_sizes, int n_in,
                              void* d_out, int out_size) {
    const float* logits = (const float*)d_in[1];
    int N = in_sizes[1] / E;                              // 8192
    int Ccap = (int)((3 * N + 2 * E - 1) / (2 * E));      // ceil(1.5*N/E) = 1536
    if (Ccap < 1) Ccap = 1;

    float* out = (float*)d_out;
    size_t D = (size_t)N * E * (size_t)Ccap;
    float* dispatch_out = out;
    float* combine_out  = out + D;
    float* scalars_out  = out + 2 * D;

    size_t n4 = (size_t)out_size >> 2;

    router_kernel<<<GRID, 256>>>((uint4*)d_out, n4, logits,
                                 dispatch_out, combine_out, scalars_out,
                                 out, out_size, N, Ccap);
}

// round 7
// speedup vs baseline: 1.0510x; 1.0510x over previous
#include <cuda_runtime.h>
#include <cstdint>
#include <cstddef>

// Router: top-1 MoE routing with capacity constraint.
// Outputs (float32): dispatch[N,8,Ccap], combine[N,8,Ccap], z, aux, div, std
//
// Graph (fork-join, 3 kernels):
//   side stream : token_kernel (keys + expert buckets + loss partials)
//                 -> rank_kernel (per-expert bucket count, ~4us, 128 slim blocks)
//   main stream : fill_kernel (805MB zero fill at DRAM roofline; its LAST ticket
//                 block spins on rank-done, then scatters <=16K nonzeros,
//                 finalizes scalars, resets counters)

#define E 8
#define MAXN 8192
#define NACC 55   // 0:z  1..8:psum  9..16:cnt  17..52:G(upper tri 36)  53:sum  54:sumsq
#define TBLOCKS 32
#define RBLOCKS 128
#define FBLOCKS 2368

__device__ unsigned long long g_fkey[MAXN];           // [e:3][p_bits:32][invidx:13]
__device__ unsigned long long g_bucket[E][MAXN];      // keys grouped by expert
__device__ int   g_bucket_cnt[E];                     // zeroed by epilogue/static init
__device__ float g_prob[MAXN];
__device__ int   g_rank[MAXN];
__device__ float g_part[TBLOCKS][NACC];
__device__ int   g_rank_done = 0;
__device__ int   g_fill_done = 0;

// --------------------------------------------------------------- token ----
__global__ void token_kernel(const float* __restrict__ logits, int N) {
    int i = blockIdx.x * blockDim.x + threadIdx.x;
    float vals[NACC];
#pragma unroll
    for (int k = 0; k < NACC; k++) vals[k] = 0.0f;

    if (i < N) {
        float4 r0 = reinterpret_cast<const float4*>(logits)[2 * i + 0];
        float4 r1 = reinterpret_cast<const float4*>(logits)[2 * i + 1];
        float raw[E] = {r0.x, r0.y, r0.z, r0.w, r1.x, r1.y, r1.z, r1.w};

        float l[E];
        float s = 0.f, s2 = 0.f;
#pragma unroll
        for (int j = 0; j < E; j++) {
            s  += raw[j];
            s2 += raw[j] * raw[j];
            float c = fminf(fmaxf(raw[j], -10.0f), 10.0f);
            l[j] = c / 1.5f;                 // IEEE div, matches JAX clip/temp
        }
        vals[53] = s;
        vals[54] = s2;

        float m = l[0]; int e = 0;
#pragma unroll
        for (int j = 1; j < E; j++) {
            if (l[j] > m) { m = l[j]; e = j; }
        }

        float sumexp = 0.f;
        float ex[E];
#pragma unroll
        for (int j = 0; j < E; j++) { ex[j] = expf(l[j] - m); sumexp += ex[j]; }
#pragma unroll
        for (int j = 0; j < E; j++) vals[1 + j] = ex[j] / sumexp;
#pragma unroll
        for (int j = 0; j < E; j++) vals[9 + j] = (e == j) ? 1.0f : 0.0f;

        float p = 1.0f / sumexp;             // probs[argmax] exactly as JAX
        g_prob[i] = p;
        // full key: expert | prob bits | inverted index (stable desc order)
        unsigned long long key = ((unsigned long long)e << 45)
                               | ((unsigned long long)__float_as_uint(p) << 13)
                               | (unsigned long long)(unsigned)(MAXN - 1 - i);
        g_fkey[i] = key;
        int pos = atomicAdd(&g_bucket_cnt[e], 1);   // order in bucket irrelevant
        g_bucket[e][pos] = key;

        float lse = m + logf(sumexp);
        vals[0] = lse * lse;

        int t = 0;
#pragma unroll
        for (int a = 0; a < E; a++)
#pragma unroll
            for (int b = a; b < E; b++) vals[17 + t++] = l[a] * l[b];
    }

    int lane = threadIdx.x & 31;
    int wid  = threadIdx.x >> 5;
#pragma unroll
    for (int k = 0; k < NACC; k++) {
        float v = vals[k];
        v += __shfl_down_sync(0xffffffffu, v, 16);
        v += __shfl_down_sync(0xffffffffu, v, 8);
        v += __shfl_down_sync(0xffffffffu, v, 4);
        v += __shfl_down_sync(0xffffffffu, v, 2);
        v += __shfl_down_sync(0xffffffffu, v, 1);
        vals[k] = v;
    }
    __shared__ float sAcc[8][NACC];
    if (lane == 0) {
#pragma unroll
        for (int k = 0; k < NACC; k++) sAcc[wid][k] = vals[k];
    }
    __syncthreads();
    for (int k = threadIdx.x; k < NACC; k += blockDim.x) {
        float v = 0.f;
#pragma unroll
        for (int w = 0; w < 8; w++) v += sAcc[w][k];
        g_part[blockIdx.x][k] = v;       // fully overwritten each call: no init
    }
}

// ---------------------------------------------------------------- rank ----
// 128 blocks x 8 warps; each warp ranks 8 tokens serially, lanes stride the
// token's expert bucket. rank_i = #{keys in bucket[e_i] greater than key_i}.
__global__ void rank_kernel(int N) {
    int lane = threadIdx.x & 31;
    int wid  = threadIdx.x >> 5;
    int base = (blockIdx.x * 8 + wid) * 8;       // 8 tokens per warp

#pragma unroll
    for (int t = 0; t < 8; t++) {
        int tok = base + t;
        if (tok >= N) break;
        unsigned long long key = g_fkey[tok];
        int e = (int)(key >> 45);
        int bc = g_bucket_cnt[e];
        const unsigned long long* bkt = g_bucket[e];
        int cnt = 0;
        for (int j = lane; j < bc; j += 32)
            cnt += (int)(bkt[j] > key);
        cnt += __shfl_down_sync(0xffffffffu, cnt, 16);
        cnt += __shfl_down_sync(0xffffffffu, cnt, 8);
        cnt += __shfl_down_sync(0xffffffffu, cnt, 4);
        cnt += __shfl_down_sync(0xffffffffu, cnt, 2);
        cnt += __shfl_down_sync(0xffffffffu, cnt, 1);
        if (lane == 0) g_rank[tok] = cnt;
    }

    __syncthreads();
    __threadfence();
    if (threadIdx.x == 0) atomicAdd(&g_rank_done, 1);
}

// ------------------------------------------------------ fill + epilogue ----
__global__ void fill_kernel(uint4* __restrict__ out4, size_t n4,
                            float* __restrict__ dispatch_out,
                            float* __restrict__ combine_out,
                            float* __restrict__ scalars_out,
                            int N, int Ccap) {
    {
        const uint4 z = make_uint4(0u, 0u, 0u, 0u);
        size_t i = (size_t)blockIdx.x * blockDim.x + threadIdx.x;
        size_t stride = (size_t)gridDim.x * blockDim.x;
        for (; i < n4; i += stride) out4[i] = z;
    }

    __syncthreads();
    __threadfence();
    __shared__ int sIsLast;
    if (threadIdx.x == 0) {
        int ticket = atomicAdd(&g_fill_done, 1);
        sIsLast = (ticket == (int)gridDim.x - 1);
    }
    __syncthreads();
    if (!sIsLast) return;

    // wait for rank results (rank finishes long before the fill)
    if (threadIdx.x == 0) {
        while (*((volatile int*)&g_rank_done) < RBLOCKS) __nanosleep(64);
    }
    __syncthreads();
    __threadfence();

    // sparse scatter: <=2 stores per token, over the just-zeroed output
    for (int tok = threadIdx.x; tok < N; tok += blockDim.x) {
        int rank = g_rank[tok];
        if (rank < Ccap) {
            unsigned long long key = g_fkey[tok];
            int e = (int)(key >> 45);
            float p = g_prob[tok];
            size_t b = ((size_t)tok * E + e) * (size_t)Ccap + (size_t)rank;
            dispatch_out[b] = 1.0f;
            combine_out[b]  = p;
        }
    }

    // fold loss partials + finalize scalars
    __shared__ float sAccF[NACC];
    if (threadIdx.x < NACC) {
        float v = 0.f;
#pragma unroll
        for (int r = 0; r < TBLOCKS; r++) v += g_part[r][threadIdx.x];
        sAccF[threadIdx.x] = v;
    }
    __syncthreads();
    if (threadIdx.x == 0) {
        float z_loss = sAccF[0] / (float)N;

        float aux = 0.f;
        for (int e = 0; e < E; e++) aux += sAccF[9 + e] * sAccF[1 + e];
        aux = aux * (float)E / ((float)N * (float)N);

        float G[E][E];
        int t = 0;
        for (int a = 0; a < E; a++)
            for (int b = a; b < E; b++) { G[a][b] = sAccF[17 + t]; G[b][a] = sAccF[17 + t]; t++; }
        float nrm[E];
        for (int a = 0; a < E; a++) nrm[a] = fmaxf(sqrtf(G[a][a]), 1e-12f);
        float div = 0.f;
        for (int a = 0; a < E; a++)
            for (int b = a + 1; b < E; b++) {
                float c = G[a][b] / (nrm[a] * nrm[b]);
                div += 2.0f * c * c;
            }
        div /= (float)(E * (E - 1));

        double M = (double)N * E;
        double sm = (double)sAccF[53], sq = (double)sAccF[54];
        double var = (sq - sm * sm / M) / (M - 1.0);

        scalars_out[0] = z_loss;
        scalars_out[1] = aux;
        scalars_out[2] = div;
        scalars_out[3] = (float)sqrt(var);

        // reset counters for the next (identical) call
        __threadfence();
        g_fill_done = 0;
        g_rank_done = 0;
#pragma unroll
        for (int e = 0; e < E; e++) g_bucket_cnt[e] = 0;
    }
}

// -------------------------------------------------------------- launch ----
extern "C" void kernel_launch(void* const* d_in, const int* in_sizes, int n_in,
                              void* d_out, int out_size) {
    const float* logits = (const float*)d_in[1];
    int N = in_sizes[1] / E;                              // 8192
    int Ccap = (int)((3 * N + 2 * E - 1) / (2 * E));      // ceil(1.5*N/E) = 1536
    if (Ccap < 1) Ccap = 1;

    float* out = (float*)d_out;
    size_t D = (size_t)N * E * (size_t)Ccap;
    float* dispatch_out = out;
    float* combine_out  = out + D;
    float* scalars_out  = out + 2 * D;

    static cudaStream_t side = nullptr;
    static cudaEvent_t  ev_fork = nullptr, ev_join = nullptr;
    if (!side) {
        cudaStreamCreateWithFlags(&side, cudaStreamNonBlocking);
        cudaEventCreateWithFlags(&ev_fork, cudaEventDisableTiming);
        cudaEventCreateWithFlags(&ev_join, cudaEventDisableTiming);
    }

    // fork: side stream computes routing while main stream fills
    cudaEventRecord(ev_fork, 0);
    cudaStreamWaitEvent(side, ev_fork, 0);
    token_kernel<<<TBLOCKS, 256, 0, side>>>(logits, N);
    rank_kernel<<<RBLOCKS, 256, 0, side>>>(N);
    cudaEventRecord(ev_join, side);

    // main: DRAM-roofline fill; last block waits on rank flag, scatters, scalars
    size_t n4 = (size_t)out_size >> 2;
    fill_kernel<<<FBLOCKS, 256>>>((uint4*)d_out, n4,
                                  dispatch_out, combine_out, scalars_out, N, Ccap);
    size_t rem = (size_t)out_size & 3;
    if (rem) cudaMemsetAsync((float*)d_out + (out_size - rem), 0, rem * sizeof(float));

    // join side stream back for capture completeness
    cudaStreamWaitEvent(0, ev_join, 0);
}

// round 8
// speedup vs baseline: 1.2569x; 1.1959x over previous
#include <cuda_runtime.h>
#include <cstdint>
#include <cstddef>

// Router: top-1 MoE routing with capacity constraint.
// Outputs (float32): dispatch[N,8,Ccap], combine[N,8,Ccap], z, aux, div, std
//
// Fork-join graph, fill kernel kept pristine (16 regs, no sync/atomics):
//   side stream : token_kernel (keys + expert buckets + loss partials, ~8us)
//                 -> rank_kernel (bucketed count, 128 slim blocks, ~4us)
//   main stream : fill_kernel (805MB zero fill at DRAM roofline, ~115us)
//   join        : scatter_kernel (<=16K sparse stores + scalars, ~7us)

#define E 8
#define MAXN 8192
#define NACC 55   // 0:z  1..8:psum  9..16:cnt  17..52:G(upper tri 36)  53:sum  54:sumsq
#define TBLOCKS 32
#define RBLOCKS 128
#define FBLOCKS 2368

__device__ unsigned long long g_fkey[MAXN];        // [e:3][p_bits:32][invidx:13]
__device__ unsigned long long g_bucket[E][MAXN];   // keys grouped by expert
__device__ int   g_bucket_cnt[E];                  // reset by scatter epilogue
__device__ float g_prob[MAXN];
__device__ int   g_rank[MAXN];
__device__ float g_part[TBLOCKS][NACC];

// ---------------------------------------------------------------- fill ----
// PRISTINE: 16 regs, no sync, no atomics -> 88% occ, ~6.5 TB/s.
__global__ void fill_kernel(uint4* __restrict__ out, size_t n4) {
    const uint4 z = make_uint4(0u, 0u, 0u, 0u);
    size_t i = (size_t)blockIdx.x * blockDim.x + threadIdx.x;
    size_t stride = (size_t)gridDim.x * blockDim.x;
    for (; i < n4; i += stride) out[i] = z;
}

// --------------------------------------------------------------- token ----
__global__ void token_kernel(const float* __restrict__ logits, int N) {
    int i = blockIdx.x * blockDim.x + threadIdx.x;
    float vals[NACC];
#pragma unroll
    for (int k = 0; k < NACC; k++) vals[k] = 0.0f;

    if (i < N) {
        float4 r0 = reinterpret_cast<const float4*>(logits)[2 * i + 0];
        float4 r1 = reinterpret_cast<const float4*>(logits)[2 * i + 1];
        float raw[E] = {r0.x, r0.y, r0.z, r0.w, r1.x, r1.y, r1.z, r1.w};

        float l[E];
        float s = 0.f, s2 = 0.f;
#pragma unroll
        for (int j = 0; j < E; j++) {
            s  += raw[j];
            s2 += raw[j] * raw[j];
            float c = fminf(fmaxf(raw[j], -10.0f), 10.0f);
            l[j] = c / 1.5f;                 // IEEE div, matches JAX clip/temp
        }
        vals[53] = s;
        vals[54] = s2;

        float m = l[0]; int e = 0;
#pragma unroll
        for (int j = 1; j < E; j++) {
            if (l[j] > m) { m = l[j]; e = j; }
        }

        float sumexp = 0.f;
        float ex[E];
#pragma unroll
        for (int j = 0; j < E; j++) { ex[j] = expf(l[j] - m); sumexp += ex[j]; }
#pragma unroll
        for (int j = 0; j < E; j++) vals[1 + j] = ex[j] / sumexp;
#pragma unroll
        for (int j = 0; j < E; j++) vals[9 + j] = (e == j) ? 1.0f : 0.0f;

        float p = 1.0f / sumexp;             // probs[argmax] exactly as JAX
        g_prob[i] = p;
        // full key: expert | prob bits | inverted index (stable desc order)
        unsigned long long key = ((unsigned long long)e << 45)
                               | ((unsigned long long)__float_as_uint(p) << 13)
                               | (unsigned long long)(unsigned)(MAXN - 1 - i);
        g_fkey[i] = key;
        int pos = atomicAdd(&g_bucket_cnt[e], 1);   // bucket order irrelevant
        g_bucket[e][pos] = key;

        float lse = m + logf(sumexp);
        vals[0] = lse * lse;

        int t = 0;
#pragma unroll
        for (int a = 0; a < E; a++)
#pragma unroll
            for (int b = a; b < E; b++) vals[17 + t++] = l[a] * l[b];
    }

    int lane = threadIdx.x & 31;
    int wid  = threadIdx.x >> 5;
#pragma unroll
    for (int k = 0; k < NACC; k++) {
        float v = vals[k];
        v += __shfl_down_sync(0xffffffffu, v, 16);
        v += __shfl_down_sync(0xffffffffu, v, 8);
        v += __shfl_down_sync(0xffffffffu, v, 4);
        v += __shfl_down_sync(0xffffffffu, v, 2);
        v += __shfl_down_sync(0xffffffffu, v, 1);
        vals[k] = v;
    }
    __shared__ float sAcc[8][NACC];
    if (lane == 0) {
#pragma unroll
        for (int k = 0; k < NACC; k++) sAcc[wid][k] = vals[k];
    }
    __syncthreads();
    for (int k = threadIdx.x; k < NACC; k += blockDim.x) {
        float v = 0.f;
#pragma unroll
        for (int w = 0; w < 8; w++) v += sAcc[w][k];
        g_part[blockIdx.x][k] = v;       // fully overwritten each call: no init
    }
}

// ---------------------------------------------------------------- rank ----
// 128 blocks x 8 warps; each warp ranks 8 tokens, lanes stride the token's
// expert bucket (~1024 keys). rank_i = #{keys in bucket[e_i] > key_i}.
__global__ void rank_kernel(int N) {
    int lane = threadIdx.x & 31;
    int wid  = threadIdx.x >> 5;
    int base = (blockIdx.x * 8 + wid) * 8;

#pragma unroll
    for (int t = 0; t < 8; t++) {
        int tok = base + t;
        if (tok >= N) break;
        unsigned long long key = g_fkey[tok];
        int e = (int)(key >> 45);
        int bc = g_bucket_cnt[e];
        const unsigned long long* bkt = g_bucket[e];
        int cnt = 0;
        for (int j = lane; j < bc; j += 32)
            cnt += (int)(bkt[j] > key);
        cnt += __shfl_down_sync(0xffffffffu, cnt, 16);
        cnt += __shfl_down_sync(0xffffffffu, cnt, 8);
        cnt += __shfl_down_sync(0xffffffffu, cnt, 4);
        cnt += __shfl_down_sync(0xffffffffu, cnt, 2);
        cnt += __shfl_down_sync(0xffffffffu, cnt, 1);
        if (lane == 0) g_rank[tok] = cnt;
    }
}

// -------------------------------------------------------------- scatter ----
__global__ void scatter_kernel(float* __restrict__ dispatch_out,
                               float* __restrict__ combine_out,
                               float* __restrict__ scalars_out,
                               int N, int Ccap) {
    int i = blockIdx.x * blockDim.x + threadIdx.x;
    if (i < N) {
        int rank = g_rank[i];
        if (rank < Ccap) {
            unsigned long long key = g_fkey[i];
            int e = (int)(key >> 45);
            float p = g_prob[i];
            size_t b = ((size_t)i * E + e) * (size_t)Ccap + (size_t)rank;
            dispatch_out[b] = 1.0f;
            combine_out[b]  = p;
        }
        // reset bucket counters for the next (identical) call
        if (i < E) g_bucket_cnt[i] = 0;
    }

    if (blockIdx.x == 0) {
        __shared__ float sAccF[NACC];
        if (threadIdx.x < NACC) {
            float v = 0.f;
#pragma unroll
            for (int r = 0; r < TBLOCKS; r++) v += g_part[r][threadIdx.x];
            sAccF[threadIdx.x] = v;
        }
        __syncthreads();
        if (threadIdx.x == 0) {
            float z_loss = sAccF[0] / (float)N;

            float aux = 0.f;
            for (int e = 0; e < E; e++) aux += sAccF[9 + e] * sAccF[1 + e];
            aux = aux * (float)E / ((float)N * (float)N);

            float G[E][E];
            int t = 0;
            for (int a = 0; a < E; a++)
                for (int b = a; b < E; b++) { G[a][b] = sAccF[17 + t]; G[b][a] = sAccF[17 + t]; t++; }
            float nrm[E];
            for (int a = 0; a < E; a++) nrm[a] = fmaxf(sqrtf(G[a][a]), 1e-12f);
            float div = 0.f;
            for (int a = 0; a < E; a++)
                for (int b = a + 1; b < E; b++) {
                    float c = G[a][b] / (nrm[a] * nrm[b]);
                    div += 2.0f * c * c;
                }
            div /= (float)(E * (E - 1));

            double M = (double)N * E;
            double sm = (double)sAccF[53], sq = (double)sAccF[54];
            double var = (sq - sm * sm / M) / (M - 1.0);

            scalars_out[0] = z_loss;
            scalars_out[1] = aux;
            scalars_out[2] = div;
            scalars_out[3] = (float)sqrt(var);
        }
    }
}

// -------------------------------------------------------------- launch ----
extern "C" void kernel_launch(void* const* d_in, const int* in_sizes, int n_in,
                              void* d_out, int out_size) {
    const float* logits = (const float*)d_in[1];
    int N = in_sizes[1] / E;                              // 8192
    int Ccap = (int)((3 * N + 2 * E - 1) / (2 * E));      // ceil(1.5*N/E) = 1536
    if (Ccap < 1) Ccap = 1;

    float* out = (float*)d_out;
    size_t D = (size_t)N * E * (size_t)Ccap;
    float* dispatch_out = out;
    float* combine_out  = out + D;
    float* scalars_out  = out + 2 * D;

    static cudaStream_t side = nullptr;
    static cudaEvent_t  ev_fork = nullptr, ev_join = nullptr;
    if (!side) {
        cudaStreamCreateWithFlags(&side, cudaStreamNonBlocking);
        cudaEventCreateWithFlags(&ev_fork, cudaEventDisableTiming);
        cudaEventCreateWithFlags(&ev_join, cudaEventDisableTiming);
    }

    // fork: thin routing work on the side stream (hidden under the fill)
    cudaEventRecord(ev_fork, 0);
    cudaStreamWaitEvent(side, ev_fork, 0);
    token_kernel<<<TBLOCKS, 256, 0, side>>>(logits, N);
    rank_kernel<<<RBLOCKS, 256, 0, side>>>(N);
    cudaEventRecord(ev_join, side);

    // main: pristine DRAM-roofline fill
    size_t n4 = (size_t)out_size >> 2;
    fill_kernel<<<FBLOCKS, 256>>>((uint4*)d_out, n4);
    size_t rem = (size_t)out_size & 3;
    if (rem) cudaMemsetAsync((float*)d_out + (out_size - rem), 0, rem * sizeof(float));

    // join: scatter after both fill and rank
    cudaStreamWaitEvent(0, ev_join, 0);
    scatter_kernel<<<(N + 255) / 256, 256>>>(dispatch_out, combine_out,
                                             scalars_out, N, Ccap);
}